// round 12
// baseline (speedup 1.0000x reference)
#include <cuda_runtime.h>
#include <cstdint>

#define NN   500000
#define EE   4000000
#define FIN  24
#define TSTR 32                     // padded T row stride (floats) = 128B
#define HH   64
#define KC   6
#define OD   6
#define EPSBN 1e-5f
#define NB   ((NN + 1023) / 1024)   // scan blocks = 489

// ---------------- static scratch ----------------
__device__ int    g_deg[NN];
__device__ float  g_dis[NN];     // deg^{-1/2}
__device__ float  g_rs[NN];      // deg^{+1/2}
__device__ float  g_inv[NN];     // 1/deg
__device__ int    g_rowptr[NN + 1];
__device__ int    g_cur[NN];
__device__ int    g_bsum[NB];
__device__ int    g_boff[NB];
__device__ int    g_ord[NN];                  // windowed degree-sorted node ids
__device__ int    g_csr[EE];                  // src index only, sorted by dst
__device__ float  g_T[6][(size_t)NN * TSTR];  // T~0..T~5 scaled space, 128B rows
__device__ float  g_h[(size_t)NN * HH];
__device__ float  g_sum[HH];
__device__ float  g_sumsq[HH];
__device__ float  g_scale[HH];
__device__ float  g_shift[HH];

// ---------------- helpers ----------------
__device__ __forceinline__ unsigned long long pack2(float lo, float hi) {
    unsigned long long r;
    asm("mov.b64 %0, {%1, %2};" : "=l"(r) : "f"(lo), "f"(hi));
    return r;
}
__device__ __forceinline__ void unpack2(unsigned long long v, float& lo, float& hi) {
    asm("mov.b64 {%0, %1}, %2;" : "=f"(lo), "=f"(hi) : "l"(v));
}
__device__ __forceinline__ void ffma2(unsigned long long& d, unsigned long long a,
                                      unsigned long long b) {
    asm("fma.rn.f32x2 %0, %1, %2, %0;" : "+l"(d) : "l"(a), "l"(b));
}
__device__ __forceinline__ void acc4(float4& a, float4 v) {
    a.x += v.x; a.y += v.y; a.z += v.z; a.w += v.w;
}

// ---------------- graph preprocessing ----------------
__global__ void k_zero() {
    int i = blockIdx.x * blockDim.x + threadIdx.x;
    if (i < NN) g_deg[i] = 0;
    if (i < HH) { g_sum[i] = 0.f; g_sumsq[i] = 0.f; }
}

__global__ void k_deg(const int4* __restrict__ col4) {
    int i = blockIdx.x * blockDim.x + threadIdx.x;
    if (i >= EE / 4) return;
    int4 c = __ldg(col4 + i);
    atomicAdd(&g_deg[c.x], 1);
    atomicAdd(&g_deg[c.y], 1);
    atomicAdd(&g_deg[c.z], 1);
    atomicAdd(&g_deg[c.w], 1);
}

__global__ __launch_bounds__(1024) void k_scan1() {
    __shared__ int s[1024];
    int tid = threadIdx.x;
    int i = blockIdx.x * 1024 + tid;
    int v = (i < NN) ? g_deg[i] : 0;
    if (i < NN) {
        if (v > 0) {
            float fv = (float)v;
            float dis = rsqrtf(fv);
            g_dis[i] = dis;
            g_rs[i]  = fv * dis;     // sqrt(deg)
            g_inv[i] = dis * dis;    // 1/deg
        } else {
            g_dis[i] = 0.f; g_rs[i] = 0.f; g_inv[i] = 0.f;
        }
    }
    s[tid] = v;
    __syncthreads();
#pragma unroll
    for (int off = 1; off < 1024; off <<= 1) {
        int t = (tid >= off) ? s[tid - off] : 0;
        __syncthreads();
        s[tid] += t;
        __syncthreads();
    }
    if (i < NN) g_rowptr[i] = s[tid] - v;
    if (tid == 1023) g_bsum[blockIdx.x] = s[1023];
}

__global__ __launch_bounds__(512) void k_scan2() {
    __shared__ int s[512];
    int tid = threadIdx.x;
    int v = (tid < NB) ? g_bsum[tid] : 0;
    s[tid] = v;
    __syncthreads();
#pragma unroll
    for (int off = 1; off < 512; off <<= 1) {
        int t = (tid >= off) ? s[tid - off] : 0;
        __syncthreads();
        s[tid] += t;
        __syncthreads();
    }
    if (tid < NB) g_boff[tid] = s[tid] - v;
    if (tid == 0) g_rowptr[NN] = EE;
}

// fused: finalize rowptr/cur + windowed degree sort + seed T~0 = D^{-1/2} x
// One 1024-thread block per 1024-node window. Bucket order within a degree is
// nondeterministic but the end-to-end result is permutation-invariant.
__global__ __launch_bounds__(1024) void k_prep(const float* __restrict__ x) {
    __shared__ int hist[64];
    __shared__ int base[64];
    int w0 = blockIdx.x * 1024;
    int tid = threadIdx.x;
    if (tid < 64) hist[tid] = 0;
    __syncthreads();
    int n = w0 + tid;
    int b = 63;
    if (n < NN) {
        // finalize rowptr
        int rp = g_rowptr[n] + g_boff[blockIdx.x];
        g_rowptr[n] = rp;
        g_cur[n] = rp;
        int d = g_deg[n];
        b = d < 63 ? d : 63;
        atomicAdd(&hist[b], 1);
        // seed T~0 row (padded)
        float dis = g_dis[n];
        const float4* xr = (const float4*)(x + (size_t)n * FIN);
        float4* tr = (float4*)(g_T[0] + (size_t)n * TSTR);
#pragma unroll
        for (int s = 0; s < 6; s++) {
            float4 v = __ldg(xr + s);
            tr[s] = make_float4(dis * v.x, dis * v.y, dis * v.z, dis * v.w);
        }
    }
    __syncthreads();
    if (tid == 0) {
        int acc = 0;
        for (int k = 0; k < 64; k++) { base[k] = acc; acc += hist[k]; }
    }
    __syncthreads();
    if (n < NN) {
        int pos = atomicAdd(&base[b], 1);
        g_ord[w0 + pos] = n;
    }
}

// scatter: CSR = src index only, 4 edges per thread
__global__ void k_scatter(const int4* __restrict__ row4, const int4* __restrict__ col4) {
    int i = blockIdx.x * blockDim.x + threadIdx.x;
    if (i >= EE / 4) return;
    int4 r = __ldg(row4 + i);
    int4 c = __ldg(col4 + i);
    g_csr[atomicAdd(&g_cur[c.x], 1)] = r.x;
    g_csr[atomicAdd(&g_cur[c.y], 1)] = r.y;
    g_csr[atomicAdd(&g_cur[c.z], 1)] = r.z;
    g_csr[atomicAdd(&g_cur[c.w], 1)] = r.w;
}

// ---------------- propagation: warp-aligned cooperative gather -------------
// 5 nodes per warp, lanes 0-29 active (lane/6 = node group, lane%6 = chunk).
// Every source row is fetched by exactly one warp instruction (no straddle).
// Nodes via g_ord: windowed degree sort -> uniform trip counts per warp.
// T~dst[c] = (-scl/deg[c]) * sum_{e into c} T~prev[src_e]  [- T~prev2[c]]
__global__ __launch_bounds__(256) void k_gather(int dsti, int prevI, int prev2I,
                                                float scl, int do_sub) {
    int t = blockIdx.x * 256 + threadIdx.x;
    int lane = t & 31;
    if (lane >= 30) return;
    int grp = (t >> 5) * 5 + lane / 6;
    if (grp >= NN) return;
    int sub = lane % 6;
    int node = __ldg(&g_ord[grp]);

    const float* src = g_T[prevI];

    int p  = __ldg(&g_rowptr[node]);
    int p1 = __ldg(&g_rowptr[node + 1]);

    float4 c0 = make_float4(0.f, 0.f, 0.f, 0.f);
    float4 c1 = c0, c2 = c0, c3 = c0;

    for (; p + 7 < p1; p += 8) {
        int r0 = __ldg(&g_csr[p]);
        int r1 = __ldg(&g_csr[p + 1]);
        int r2 = __ldg(&g_csr[p + 2]);
        int r3 = __ldg(&g_csr[p + 3]);
        int r4 = __ldg(&g_csr[p + 4]);
        int r5 = __ldg(&g_csr[p + 5]);
        int r6 = __ldg(&g_csr[p + 6]);
        int r7 = __ldg(&g_csr[p + 7]);
        float4 v0 = __ldg((const float4*)(src + (size_t)r0 * TSTR) + sub);
        float4 v1 = __ldg((const float4*)(src + (size_t)r1 * TSTR) + sub);
        float4 v2 = __ldg((const float4*)(src + (size_t)r2 * TSTR) + sub);
        float4 v3 = __ldg((const float4*)(src + (size_t)r3 * TSTR) + sub);
        float4 v4 = __ldg((const float4*)(src + (size_t)r4 * TSTR) + sub);
        float4 v5 = __ldg((const float4*)(src + (size_t)r5 * TSTR) + sub);
        float4 v6 = __ldg((const float4*)(src + (size_t)r6 * TSTR) + sub);
        float4 v7 = __ldg((const float4*)(src + (size_t)r7 * TSTR) + sub);
        acc4(c0, v0); acc4(c1, v1); acc4(c2, v2); acc4(c3, v3);
        acc4(c0, v4); acc4(c1, v5); acc4(c2, v6); acc4(c3, v7);
    }
    for (; p < p1; p++) {
        int r0 = __ldg(&g_csr[p]);
        float4 v0 = __ldg((const float4*)(src + (size_t)r0 * TSTR) + sub);
        acc4(c0, v0);
    }

    acc4(c0, c1); acc4(c2, c3); acc4(c0, c2);
    float coef = -scl * __ldg(&g_inv[node]);
    float ax = coef * c0.x, ay = coef * c0.y, az = coef * c0.z, aw = coef * c0.w;
    if (do_sub) {
        float4 q = __ldg((const float4*)(g_T[prev2I] + (size_t)node * TSTR) + sub);
        ax -= q.x; ay -= q.y; az -= q.z; aw -= q.w;
    }
    ((float4*)(g_T[dsti] + (size_t)node * TSTR))[sub] = make_float4(ax, ay, az, aw);
}

// ---------------- h = [x | rs*T~1..rs*T~5] @ W[144,64] + b1 ; + BN stats ----------
__global__ __launch_bounds__(128) void k_gemm(const float* __restrict__ x,
                                              const float* __restrict__ W1,
                                              const float* __restrict__ b1) {
    __shared__ float sW[KC * FIN * HH];   // 36 KB
    __shared__ float sRs[4][HH];
    __shared__ float sRq[4][HH];

    int tid = threadIdx.x;
    for (int i = tid; i < KC * FIN * HH; i += 128) sW[i] = W1[i];
    __syncthreads();

    int half = tid & 1;
    int n0 = blockIdx.x * 128 + (tid >> 1) * 2;
    int n1 = n0 + 1;
    bool v0 = (n0 < NN), v1 = (n1 < NN);

    float rs0 = v0 ? __ldg(&g_rs[n0]) : 0.f;
    float rs1 = v1 ? __ldg(&g_rs[n1]) : 0.f;
    bool z0 = v0 && (__ldg(&g_deg[n0]) == 0);
    bool z1 = v1 && (__ldg(&g_deg[n1]) == 0);

    unsigned long long acc0[16], acc1[16];
#pragma unroll
    for (int j = 0; j < 16; j++) { acc0[j] = 0ull; acc1[j] = 0ull; }

#pragma unroll
    for (int k = 0; k < KC; k++) {
        const float* base = (k == 0 ? x : g_T[k]);
        int str = (k == 0 ? FIN : TSTR);
        const float4* s40 = (const float4*)(base + (size_t)n0 * str);
        const float4* s41 = (const float4*)(base + (size_t)n1 * str);
        float m0 = (k == 0) ? 1.f : rs0;
        float m1 = (k == 0) ? 1.f : rs1;
#pragma unroll
        for (int i4 = 0; i4 < 6; i4++) {
            float4 a = v0 ? __ldg(s40 + i4) : make_float4(0.f, 0.f, 0.f, 0.f);
            float4 b = v1 ? __ldg(s41 + i4) : make_float4(0.f, 0.f, 0.f, 0.f);
            float av[4] = {m0 * a.x, m0 * a.y, m0 * a.z, m0 * a.w};
            float bv[4] = {m1 * b.x, m1 * b.y, m1 * b.z, m1 * b.w};
#pragma unroll
            for (int t = 0; t < 4; t++) {
                int i = i4 * 4 + t;
                unsigned long long pa = pack2(av[t], av[t]);
                unsigned long long pb = pack2(bv[t], bv[t]);
                const unsigned long long* wr =
                    (const unsigned long long*)&sW[(k * FIN + i) * HH + half * 32];
#pragma unroll
                for (int j = 0; j < 16; j++) {
                    unsigned long long wj = wr[j];
                    ffma2(acc0[j], pa, wj);
                    ffma2(acc1[j], pb, wj);
                }
            }
        }
    }

    // rare deg==0 correction: scaled T~ are zero there, but true T2=-x, T4=+x
    if (z0 | z1) {
        for (int i = 0; i < FIN; i++) {
            float x0 = z0 ? __ldg(&x[(size_t)n0 * FIN + i]) : 0.f;
            float x1 = z1 ? __ldg(&x[(size_t)n1 * FIN + i]) : 0.f;
            const float2* w2 = (const float2*)&sW[(2 * FIN + i) * HH + half * 32];
            const float2* w4 = (const float2*)&sW[(4 * FIN + i) * HH + half * 32];
            for (int j = 0; j < 16; j++) {
                float2 a2 = w2[j], a4 = w4[j];
                unsigned long long wd = pack2(a4.x - a2.x, a4.y - a2.y);
                if (z0) ffma2(acc0[j], pack2(x0, x0), wd);
                if (z1) ffma2(acc1[j], pack2(x1, x1), wd);
            }
        }
    }

    float s[32], q[32];
#pragma unroll
    for (int j = 0; j < 16; j++) {
        float b0 = __ldg(&b1[half * 32 + 2 * j]);
        float b1v = __ldg(&b1[half * 32 + 2 * j + 1]);
        float a0, a1c, c0, c1;
        unpack2(acc0[j], a0, a1c);
        unpack2(acc1[j], c0, c1);
        a0 += b0; a1c += b1v; c0 += b0; c1 += b1v;
        s[2 * j]     = (v0 ? a0 : 0.f) + (v1 ? c0 : 0.f);
        s[2 * j + 1] = (v0 ? a1c : 0.f) + (v1 ? c1 : 0.f);
        q[2 * j]     = (v0 ? a0 * a0 : 0.f) + (v1 ? c0 * c0 : 0.f);
        q[2 * j + 1] = (v0 ? a1c * a1c : 0.f) + (v1 ? c1 * c1 : 0.f);
        if (v0) ((float2*)(g_h + (size_t)n0 * HH + half * 32))[j] = make_float2(a0, a1c);
        if (v1) ((float2*)(g_h + (size_t)n1 * HH + half * 32))[j] = make_float2(c0, c1);
    }

    int lane = tid & 31, wid = tid >> 5;
#pragma unroll
    for (int j = 0; j < 32; j++) {
        float sv = s[j], qv = q[j];
#pragma unroll
        for (int off = 2; off < 32; off <<= 1) {
            sv += __shfl_xor_sync(0xffffffffu, sv, off);
            qv += __shfl_xor_sync(0xffffffffu, qv, off);
        }
        if ((lane >> 1) == 0) {
            sRs[wid][(lane & 1) * 32 + j] = sv;
            sRq[wid][(lane & 1) * 32 + j] = qv;
        }
    }
    __syncthreads();
    if (tid < HH) {
        float a = sRs[0][tid] + sRs[1][tid] + sRs[2][tid] + sRs[3][tid];
        float b = sRq[0][tid] + sRq[1][tid] + sRq[2][tid] + sRq[3][tid];
        atomicAdd(&g_sum[tid], a);
        atomicAdd(&g_sumsq[tid], b);
    }
}

__global__ void k_bnparam(const float* __restrict__ gamma, const float* __restrict__ beta) {
    int j = threadIdx.x;
    if (j < HH) {
        float inv_n = 1.f / (float)NN;
        float mean = g_sum[j] * inv_n;
        float var  = g_sumsq[j] * inv_n - mean * mean;
        float rstd = rsqrtf(var + EPSBN);
        float sc = gamma[j] * rstd;
        g_scale[j] = sc;
        g_shift[j] = beta[j] - mean * sc;
    }
}

__global__ __launch_bounds__(256) void k_final(const float* __restrict__ Wmix,
                                               const float* __restrict__ bmix,
                                               float* __restrict__ out) {
    __shared__ float sWm[HH * OD];
    __shared__ float sSc[HH], sSh[HH], sB[OD];
    int tid = threadIdx.x;
    for (int i = tid; i < HH * OD; i += 256) sWm[i] = Wmix[i];
    if (tid < HH) { sSc[tid] = g_scale[tid]; sSh[tid] = g_shift[tid]; }
    if (tid < OD) sB[tid] = bmix[tid];
    __syncthreads();

    int n = blockIdx.x * 256 + tid;
    if (n >= NN) return;

    float o0 = sB[0], o1 = sB[1], o2 = sB[2], o3 = sB[3], o4 = sB[4], o5 = sB[5];
    const float4* hp = (const float4*)(g_h + (size_t)n * HH);
#pragma unroll
    for (int j4 = 0; j4 < 16; j4++) {
        float4 hv = hp[j4];
        float hv4[4] = {hv.x, hv.y, hv.z, hv.w};
#pragma unroll
        for (int t = 0; t < 4; t++) {
            int j = 4 * j4 + t;
            float val = fmaxf(hv4[t] * sSc[j] + sSh[j], 0.f);
            const float* wm = &sWm[j * OD];
            o0 += val * wm[0]; o1 += val * wm[1]; o2 += val * wm[2];
            o3 += val * wm[3]; o4 += val * wm[4]; o5 += val * wm[5];
        }
    }
    float* op = out + (size_t)n * OD;
    op[0] = o0; op[1] = o1; op[2] = o2; op[3] = o3; op[4] = o4; op[5] = o5;
}

// ---------------- launch ----------------
extern "C" void kernel_launch(void* const* d_in, const int* in_sizes, int n_in,
                              void* d_out, int out_size) {
    const float* x     = (const float*)d_in[0];
    const int*   ei    = (const int*)  d_in[1];
    const float* W1    = (const float*)d_in[2];
    const float* b1    = (const float*)d_in[3];
    const float* gamma = (const float*)d_in[4];
    const float* beta  = (const float*)d_in[5];
    const float* Wmix  = (const float*)d_in[6];
    const float* bmix  = (const float*)d_in[7];
    float* out = (float*)d_out;

    const int* row = ei;
    const int* col = ei + EE;

    const int TB = 256;
    int gN  = (NN + TB - 1) / TB;
    int gE4 = (EE / 4 + TB - 1) / TB;
    int nWarps = (NN + 4) / 5;                    // 5 nodes per warp
    int gG  = (nWarps * 32 + TB - 1) / TB;

    k_zero<<<gN, TB>>>();
    k_deg<<<gE4, TB>>>((const int4*)col);
    k_scan1<<<NB, 1024>>>();
    k_scan2<<<1, 512>>>();
    k_prep<<<NB, 1024>>>(x);
    k_scatter<<<gE4, TB>>>((const int4*)row, (const int4*)col);

    // scaled-space Chebyshev recurrence
    k_gather<<<gG, TB>>>(1, 0, 0, 1.f, 0);   // T~1 = -(1/deg) sum T~0
    k_gather<<<gG, TB>>>(2, 1, 0, 2.f, 1);   // T~2 = -(2/deg) sum T~1 - T~0
    k_gather<<<gG, TB>>>(3, 2, 1, 2.f, 1);
    k_gather<<<gG, TB>>>(4, 3, 2, 2.f, 1);
    k_gather<<<gG, TB>>>(5, 4, 3, 2.f, 1);

    k_gemm<<<(NN + 127) / 128, 128>>>(x, W1, b1);
    k_bnparam<<<1, HH>>>(gamma, beta);
    k_final<<<gN, TB>>>(Wmix, bmix, out);
}

// round 13
// speedup vs baseline: 1.1156x; 1.1156x over previous
#include <cuda_runtime.h>
#include <cstdint>

#define NN   500000
#define EE   4000000
#define FIN  24
#define TSTR 32                     // padded T row stride (floats) = 128B
#define HH   64
#define KC   6
#define OD   6
#define EPSBN 1e-5f
#define NB   ((NN + 1023) / 1024)   // scan blocks = 489

// ---------------- static scratch ----------------
__device__ int    g_deg[NN];
__device__ float  g_dis[NN];     // deg^{-1/2}
__device__ float  g_rs[NN];      // deg^{+1/2}
__device__ float  g_inv[NN];     // 1/deg
__device__ int    g_rowptr[NN + 1];
__device__ int    g_cur[NN];
__device__ int    g_bsum[NB];
__device__ int    g_boff[NB];
__device__ int    g_ord[NN];                  // windowed degree-sorted node ids
__device__ int    g_csr[EE];                  // src index only, sorted by dst
__device__ float  g_T[6][(size_t)NN * TSTR];  // T~0..T~5 scaled space, 128B rows
__device__ float  g_h[(size_t)NN * HH];
__device__ float  g_sum[HH];
__device__ float  g_sumsq[HH];
__device__ float  g_scale[HH];
__device__ float  g_shift[HH];

// ---------------- helpers ----------------
__device__ __forceinline__ unsigned long long pack2(float lo, float hi) {
    unsigned long long r;
    asm("mov.b64 %0, {%1, %2};" : "=l"(r) : "f"(lo), "f"(hi));
    return r;
}
__device__ __forceinline__ void unpack2(unsigned long long v, float& lo, float& hi) {
    asm("mov.b64 {%0, %1}, %2;" : "=f"(lo), "=f"(hi) : "l"(v));
}
__device__ __forceinline__ void ffma2(unsigned long long& d, unsigned long long a,
                                      unsigned long long b) {
    asm("fma.rn.f32x2 %0, %1, %2, %0;" : "+l"(d) : "l"(a), "l"(b));
}

// ---------------- graph preprocessing ----------------
__global__ void k_zero() {
    int i = blockIdx.x * blockDim.x + threadIdx.x;
    if (i < NN) g_deg[i] = 0;
    if (i < HH) { g_sum[i] = 0.f; g_sumsq[i] = 0.f; }
}

__global__ void k_deg(const int4* __restrict__ col4) {
    int i = blockIdx.x * blockDim.x + threadIdx.x;
    if (i >= EE / 4) return;
    int4 c = __ldg(col4 + i);
    atomicAdd(&g_deg[c.x], 1);
    atomicAdd(&g_deg[c.y], 1);
    atomicAdd(&g_deg[c.z], 1);
    atomicAdd(&g_deg[c.w], 1);
}

__global__ __launch_bounds__(1024) void k_scan1() {
    __shared__ int s[1024];
    int tid = threadIdx.x;
    int i = blockIdx.x * 1024 + tid;
    int v = (i < NN) ? g_deg[i] : 0;
    if (i < NN) {
        if (v > 0) {
            float fv = (float)v;
            float dis = rsqrtf(fv);
            g_dis[i] = dis;
            g_rs[i]  = fv * dis;     // sqrt(deg)
            g_inv[i] = dis * dis;    // 1/deg
        } else {
            g_dis[i] = 0.f; g_rs[i] = 0.f; g_inv[i] = 0.f;
        }
    }
    s[tid] = v;
    __syncthreads();
#pragma unroll
    for (int off = 1; off < 1024; off <<= 1) {
        int t = (tid >= off) ? s[tid - off] : 0;
        __syncthreads();
        s[tid] += t;
        __syncthreads();
    }
    if (i < NN) g_rowptr[i] = s[tid] - v;
    if (tid == 1023) g_bsum[blockIdx.x] = s[1023];
}

__global__ __launch_bounds__(512) void k_scan2() {
    __shared__ int s[512];
    int tid = threadIdx.x;
    int v = (tid < NB) ? g_bsum[tid] : 0;
    s[tid] = v;
    __syncthreads();
#pragma unroll
    for (int off = 1; off < 512; off <<= 1) {
        int t = (tid >= off) ? s[tid - off] : 0;
        __syncthreads();
        s[tid] += t;
        __syncthreads();
    }
    if (tid < NB) g_boff[tid] = s[tid] - v;
    if (tid == 0) g_rowptr[NN] = EE;
}

// fused: finalize rowptr/cur + windowed degree sort + seed T~0 = D^{-1/2} x
// One 1024-thread block per 1024-node window. Bucket fill order within a degree
// is nondeterministic but the end-to-end result is permutation-invariant.
__global__ __launch_bounds__(1024) void k_prep(const float* __restrict__ x) {
    __shared__ int hist[64];
    __shared__ int base[64];
    int w0 = blockIdx.x * 1024;
    int tid = threadIdx.x;
    if (tid < 64) hist[tid] = 0;
    __syncthreads();
    int n = w0 + tid;
    int b = 63;
    if (n < NN) {
        int rp = g_rowptr[n] + g_boff[blockIdx.x];
        g_rowptr[n] = rp;
        g_cur[n] = rp;
        int d = g_deg[n];
        b = d < 63 ? d : 63;
        atomicAdd(&hist[b], 1);
        // seed T~0 row (padded)
        float dis = g_dis[n];
        const float4* xr = (const float4*)(x + (size_t)n * FIN);
        float4* tr = (float4*)(g_T[0] + (size_t)n * TSTR);
#pragma unroll
        for (int s = 0; s < 6; s++) {
            float4 v = __ldg(xr + s);
            tr[s] = make_float4(dis * v.x, dis * v.y, dis * v.z, dis * v.w);
        }
    }
    __syncthreads();
    if (tid == 0) {
        int acc = 0;
        for (int k = 0; k < 64; k++) { base[k] = acc; acc += hist[k]; }
    }
    __syncthreads();
    if (n < NN) {
        int pos = atomicAdd(&base[b], 1);
        g_ord[w0 + pos] = n;
    }
}

// scatter: CSR = src index only, 4 edges per thread
__global__ void k_scatter(const int4* __restrict__ row4, const int4* __restrict__ col4) {
    int i = blockIdx.x * blockDim.x + threadIdx.x;
    if (i >= EE / 4) return;
    int4 r = __ldg(row4 + i);
    int4 c = __ldg(col4 + i);
    g_csr[atomicAdd(&g_cur[c.x], 1)] = r.x;
    g_csr[atomicAdd(&g_cur[c.y], 1)] = r.y;
    g_csr[atomicAdd(&g_cur[c.z], 1)] = r.z;
    g_csr[atomicAdd(&g_cur[c.w], 1)] = r.w;
}

// ---------------- propagation: cooperative gather (scaled space) ----------------
// 6 lanes per node (dense, no idle lanes); nodes via g_ord so adjacent groups
// have equal degree (windowed sort) -> minimal intra-warp imbalance.
// T~dst[c] = (-scl/deg[c]) * sum_{e into c} T~prev[src_e]  [- T~prev2[c]]
__global__ __launch_bounds__(256) void k_gather(int dsti, int prevI, int prev2I,
                                                float scl, int do_sub) {
    int t = blockIdx.x * blockDim.x + threadIdx.x;
    int grp = t / 6;
    if (grp >= NN) return;
    int sub = t - grp * 6;
    int node = __ldg(&g_ord[grp]);

    const float* src = g_T[prevI];

    int p  = __ldg(&g_rowptr[node]);
    int p1 = __ldg(&g_rowptr[node + 1]);

    float ax = 0.f, ay = 0.f, az = 0.f, aw = 0.f;   // chain A
    float bx = 0.f, by = 0.f, bz = 0.f, bw = 0.f;   // chain B

    for (; p + 3 < p1; p += 4) {
        int r0 = __ldg(&g_csr[p]);
        int r1 = __ldg(&g_csr[p + 1]);
        int r2 = __ldg(&g_csr[p + 2]);
        int r3 = __ldg(&g_csr[p + 3]);
        float4 v0 = __ldg((const float4*)(src + (size_t)r0 * TSTR) + sub);
        float4 v1 = __ldg((const float4*)(src + (size_t)r1 * TSTR) + sub);
        float4 v2 = __ldg((const float4*)(src + (size_t)r2 * TSTR) + sub);
        float4 v3 = __ldg((const float4*)(src + (size_t)r3 * TSTR) + sub);
        ax += v0.x + v2.x; ay += v0.y + v2.y; az += v0.z + v2.z; aw += v0.w + v2.w;
        bx += v1.x + v3.x; by += v1.y + v3.y; bz += v1.z + v3.z; bw += v1.w + v3.w;
    }
    for (; p < p1; p++) {
        int r0 = __ldg(&g_csr[p]);
        float4 v0 = __ldg((const float4*)(src + (size_t)r0 * TSTR) + sub);
        ax += v0.x; ay += v0.y; az += v0.z; aw += v0.w;
    }

    float coef = -scl * __ldg(&g_inv[node]);
    ax = coef * (ax + bx); ay = coef * (ay + by);
    az = coef * (az + bz); aw = coef * (aw + bw);
    if (do_sub) {
        float4 q = __ldg((const float4*)(g_T[prev2I] + (size_t)node * TSTR) + sub);
        ax -= q.x; ay -= q.y; az -= q.z; aw -= q.w;
    }
    ((float4*)(g_T[dsti] + (size_t)node * TSTR))[sub] = make_float4(ax, ay, az, aw);
}

// ---------------- h = [x | rs*T~1..rs*T~5] @ W[144,64] + b1 ; + BN stats ----------
__global__ __launch_bounds__(128) void k_gemm(const float* __restrict__ x,
                                              const float* __restrict__ W1,
                                              const float* __restrict__ b1) {
    __shared__ float sW[KC * FIN * HH];   // 36 KB
    __shared__ float sRs[4][HH];
    __shared__ float sRq[4][HH];

    int tid = threadIdx.x;
    for (int i = tid; i < KC * FIN * HH; i += 128) sW[i] = W1[i];
    __syncthreads();

    int half = tid & 1;
    int n0 = blockIdx.x * 128 + (tid >> 1) * 2;
    int n1 = n0 + 1;
    bool v0 = (n0 < NN), v1 = (n1 < NN);

    float rs0 = v0 ? __ldg(&g_rs[n0]) : 0.f;
    float rs1 = v1 ? __ldg(&g_rs[n1]) : 0.f;
    bool z0 = v0 && (__ldg(&g_deg[n0]) == 0);
    bool z1 = v1 && (__ldg(&g_deg[n1]) == 0);

    unsigned long long acc0[16], acc1[16];
#pragma unroll
    for (int j = 0; j < 16; j++) { acc0[j] = 0ull; acc1[j] = 0ull; }

#pragma unroll
    for (int k = 0; k < KC; k++) {
        const float* base = (k == 0 ? x : g_T[k]);
        int str = (k == 0 ? FIN : TSTR);
        const float4* s40 = (const float4*)(base + (size_t)n0 * str);
        const float4* s41 = (const float4*)(base + (size_t)n1 * str);
        float m0 = (k == 0) ? 1.f : rs0;
        float m1 = (k == 0) ? 1.f : rs1;
#pragma unroll
        for (int i4 = 0; i4 < 6; i4++) {
            float4 a = v0 ? __ldg(s40 + i4) : make_float4(0.f, 0.f, 0.f, 0.f);
            float4 b = v1 ? __ldg(s41 + i4) : make_float4(0.f, 0.f, 0.f, 0.f);
            float av[4] = {m0 * a.x, m0 * a.y, m0 * a.z, m0 * a.w};
            float bv[4] = {m1 * b.x, m1 * b.y, m1 * b.z, m1 * b.w};
#pragma unroll
            for (int t = 0; t < 4; t++) {
                int i = i4 * 4 + t;
                unsigned long long pa = pack2(av[t], av[t]);
                unsigned long long pb = pack2(bv[t], bv[t]);
                const unsigned long long* wr =
                    (const unsigned long long*)&sW[(k * FIN + i) * HH + half * 32];
#pragma unroll
                for (int j = 0; j < 16; j++) {
                    unsigned long long wj = wr[j];
                    ffma2(acc0[j], pa, wj);
                    ffma2(acc1[j], pb, wj);
                }
            }
        }
    }

    // rare deg==0 correction: scaled T~ are zero there, but true T2=-x, T4=+x
    if (z0 | z1) {
        for (int i = 0; i < FIN; i++) {
            float x0 = z0 ? __ldg(&x[(size_t)n0 * FIN + i]) : 0.f;
            float x1 = z1 ? __ldg(&x[(size_t)n1 * FIN + i]) : 0.f;
            const float2* w2 = (const float2*)&sW[(2 * FIN + i) * HH + half * 32];
            const float2* w4 = (const float2*)&sW[(4 * FIN + i) * HH + half * 32];
            for (int j = 0; j < 16; j++) {
                float2 a2 = w2[j], a4 = w4[j];
                unsigned long long wd = pack2(a4.x - a2.x, a4.y - a2.y);
                if (z0) ffma2(acc0[j], pack2(x0, x0), wd);
                if (z1) ffma2(acc1[j], pack2(x1, x1), wd);
            }
        }
    }

    float s[32], q[32];
#pragma unroll
    for (int j = 0; j < 16; j++) {
        float b0 = __ldg(&b1[half * 32 + 2 * j]);
        float b1v = __ldg(&b1[half * 32 + 2 * j + 1]);
        float a0, a1c, c0, c1;
        unpack2(acc0[j], a0, a1c);
        unpack2(acc1[j], c0, c1);
        a0 += b0; a1c += b1v; c0 += b0; c1 += b1v;
        s[2 * j]     = (v0 ? a0 : 0.f) + (v1 ? c0 : 0.f);
        s[2 * j + 1] = (v0 ? a1c : 0.f) + (v1 ? c1 : 0.f);
        q[2 * j]     = (v0 ? a0 * a0 : 0.f) + (v1 ? c0 * c0 : 0.f);
        q[2 * j + 1] = (v0 ? a1c * a1c : 0.f) + (v1 ? c1 * c1 : 0.f);
        if (v0) ((float2*)(g_h + (size_t)n0 * HH + half * 32))[j] = make_float2(a0, a1c);
        if (v1) ((float2*)(g_h + (size_t)n1 * HH + half * 32))[j] = make_float2(c0, c1);
    }

    int lane = tid & 31, wid = tid >> 5;
#pragma unroll
    for (int j = 0; j < 32; j++) {
        float sv = s[j], qv = q[j];
#pragma unroll
        for (int off = 2; off < 32; off <<= 1) {
            sv += __shfl_xor_sync(0xffffffffu, sv, off);
            qv += __shfl_xor_sync(0xffffffffu, qv, off);
        }
        if ((lane >> 1) == 0) {
            sRs[wid][(lane & 1) * 32 + j] = sv;
            sRq[wid][(lane & 1) * 32 + j] = qv;
        }
    }
    __syncthreads();
    if (tid < HH) {
        float a = sRs[0][tid] + sRs[1][tid] + sRs[2][tid] + sRs[3][tid];
        float b = sRq[0][tid] + sRq[1][tid] + sRq[2][tid] + sRq[3][tid];
        atomicAdd(&g_sum[tid], a);
        atomicAdd(&g_sumsq[tid], b);
    }
}

__global__ void k_bnparam(const float* __restrict__ gamma, const float* __restrict__ beta) {
    int j = threadIdx.x;
    if (j < HH) {
        float inv_n = 1.f / (float)NN;
        float mean = g_sum[j] * inv_n;
        float var  = g_sumsq[j] * inv_n - mean * mean;
        float rstd = rsqrtf(var + EPSBN);
        float sc = gamma[j] * rstd;
        g_scale[j] = sc;
        g_shift[j] = beta[j] - mean * sc;
    }
}

__global__ __launch_bounds__(256) void k_final(const float* __restrict__ Wmix,
                                               const float* __restrict__ bmix,
                                               float* __restrict__ out) {
    __shared__ float sWm[HH * OD];
    __shared__ float sSc[HH], sSh[HH], sB[OD];
    int tid = threadIdx.x;
    for (int i = tid; i < HH * OD; i += 256) sWm[i] = Wmix[i];
    if (tid < HH) { sSc[tid] = g_scale[tid]; sSh[tid] = g_shift[tid]; }
    if (tid < OD) sB[tid] = bmix[tid];
    __syncthreads();

    int n = blockIdx.x * 256 + tid;
    if (n >= NN) return;

    float o0 = sB[0], o1 = sB[1], o2 = sB[2], o3 = sB[3], o4 = sB[4], o5 = sB[5];
    const float4* hp = (const float4*)(g_h + (size_t)n * HH);
#pragma unroll
    for (int j4 = 0; j4 < 16; j4++) {
        float4 hv = hp[j4];
        float hv4[4] = {hv.x, hv.y, hv.z, hv.w};
#pragma unroll
        for (int t = 0; t < 4; t++) {
            int j = 4 * j4 + t;
            float val = fmaxf(hv4[t] * sSc[j] + sSh[j], 0.f);
            const float* wm = &sWm[j * OD];
            o0 += val * wm[0]; o1 += val * wm[1]; o2 += val * wm[2];
            o3 += val * wm[3]; o4 += val * wm[4]; o5 += val * wm[5];
        }
    }
    float* op = out + (size_t)n * OD;
    op[0] = o0; op[1] = o1; op[2] = o2; op[3] = o3; op[4] = o4; op[5] = o5;
}

// ---------------- launch ----------------
extern "C" void kernel_launch(void* const* d_in, const int* in_sizes, int n_in,
                              void* d_out, int out_size) {
    const float* x     = (const float*)d_in[0];
    const int*   ei    = (const int*)  d_in[1];
    const float* W1    = (const float*)d_in[2];
    const float* b1    = (const float*)d_in[3];
    const float* gamma = (const float*)d_in[4];
    const float* beta  = (const float*)d_in[5];
    const float* Wmix  = (const float*)d_in[6];
    const float* bmix  = (const float*)d_in[7];
    float* out = (float*)d_out;

    const int* row = ei;
    const int* col = ei + EE;

    const int TB = 256;
    int gN  = (NN + TB - 1) / TB;
    int gE4 = (EE / 4 + TB - 1) / TB;
    int gG  = (6 * NN + TB - 1) / TB;

    k_zero<<<gN, TB>>>();
    k_deg<<<gE4, TB>>>((const int4*)col);
    k_scan1<<<NB, 1024>>>();
    k_scan2<<<1, 512>>>();
    k_prep<<<NB, 1024>>>(x);
    k_scatter<<<gE4, TB>>>((const int4*)row, (const int4*)col);

    // scaled-space Chebyshev recurrence
    k_gather<<<gG, TB>>>(1, 0, 0, 1.f, 0);   // T~1 = -(1/deg) sum T~0
    k_gather<<<gG, TB>>>(2, 1, 0, 2.f, 1);   // T~2 = -(2/deg) sum T~1 - T~0
    k_gather<<<gG, TB>>>(3, 2, 1, 2.f, 1);
    k_gather<<<gG, TB>>>(4, 3, 2, 2.f, 1);
    k_gather<<<gG, TB>>>(5, 4, 3, 2.f, 1);

    k_gemm<<<(NN + 127) / 128, 128>>>(x, W1, b1);
    k_bnparam<<<1, HH>>>(gamma, beta);
    k_final<<<gN, TB>>>(Wmix, bmix, out);
}

// round 14
// speedup vs baseline: 1.1656x; 1.0448x over previous
#include <cuda_runtime.h>
#include <cstdint>

#define NN   500000
#define EE   4000000
#define FIN  24
#define TSTR 32                     // padded T row stride (floats) = 128B
#define HH   64
#define KC   6
#define OD   6
#define EPSBN 1e-5f
#define NB   ((NN + 1023) / 1024)   // scan blocks = 489

// ---------------- static scratch ----------------
__device__ int    g_deg[NN];
__device__ float  g_dis[NN];     // deg^{-1/2}
__device__ float  g_rs[NN];      // deg^{+1/2}
__device__ float  g_inv[NN];     // 1/deg
__device__ int    g_rowptr[NN + 1];
__device__ int    g_cur[NN];
__device__ int    g_bsum[NB];
__device__ int    g_boff[NB];
__device__ int    g_ord[NN];                  // windowed degree-sorted node ids
__device__ int    g_csr[EE];                  // src index only, sorted by dst
__device__ float  g_T[6][(size_t)NN * TSTR];  // T~0..T~5 scaled space, 128B rows
__device__ float  g_h[(size_t)NN * HH];
__device__ float  g_sum[HH];
__device__ float  g_sumsq[HH];
__device__ float  g_scale[HH];
__device__ float  g_shift[HH];

// ---------------- helpers ----------------
__device__ __forceinline__ unsigned long long pack2(float lo, float hi) {
    unsigned long long r;
    asm("mov.b64 %0, {%1, %2};" : "=l"(r) : "f"(lo), "f"(hi));
    return r;
}
__device__ __forceinline__ void unpack2(unsigned long long v, float& lo, float& hi) {
    asm("mov.b64 {%0, %1}, %2;" : "=f"(lo), "=f"(hi) : "l"(v));
}
__device__ __forceinline__ void ffma2(unsigned long long& d, unsigned long long a,
                                      unsigned long long b) {
    asm("fma.rn.f32x2 %0, %1, %2, %0;" : "+l"(d) : "l"(a), "l"(b));
}

// ---------------- graph preprocessing ----------------
__global__ void k_zero() {
    int i = blockIdx.x * blockDim.x + threadIdx.x;
    if (i < NN) g_deg[i] = 0;
    if (i < HH) { g_sum[i] = 0.f; g_sumsq[i] = 0.f; }
}

__global__ void k_deg(const int4* __restrict__ col4) {
    int i = blockIdx.x * blockDim.x + threadIdx.x;
    if (i >= EE / 4) return;
    int4 c = __ldg(col4 + i);
    atomicAdd(&g_deg[c.x], 1);
    atomicAdd(&g_deg[c.y], 1);
    atomicAdd(&g_deg[c.z], 1);
    atomicAdd(&g_deg[c.w], 1);
}

__global__ __launch_bounds__(1024) void k_scan1() {
    __shared__ int s[1024];
    int tid = threadIdx.x;
    int i = blockIdx.x * 1024 + tid;
    int v = (i < NN) ? g_deg[i] : 0;
    if (i < NN) {
        if (v > 0) {
            float fv = (float)v;
            float dis = rsqrtf(fv);
            g_dis[i] = dis;
            g_rs[i]  = fv * dis;     // sqrt(deg)
            g_inv[i] = dis * dis;    // 1/deg
        } else {
            g_dis[i] = 0.f; g_rs[i] = 0.f; g_inv[i] = 0.f;
        }
    }
    s[tid] = v;
    __syncthreads();
#pragma unroll
    for (int off = 1; off < 1024; off <<= 1) {
        int t = (tid >= off) ? s[tid - off] : 0;
        __syncthreads();
        s[tid] += t;
        __syncthreads();
    }
    if (i < NN) g_rowptr[i] = s[tid] - v;
    if (tid == 1023) g_bsum[blockIdx.x] = s[1023];
}

__global__ __launch_bounds__(512) void k_scan2() {
    __shared__ int s[512];
    int tid = threadIdx.x;
    int v = (tid < NB) ? g_bsum[tid] : 0;
    s[tid] = v;
    __syncthreads();
#pragma unroll
    for (int off = 1; off < 512; off <<= 1) {
        int t = (tid >= off) ? s[tid - off] : 0;
        __syncthreads();
        s[tid] += t;
        __syncthreads();
    }
    if (tid < NB) g_boff[tid] = s[tid] - v;
    if (tid == 0) g_rowptr[NN] = EE;
}

// fused: finalize rowptr/cur + windowed degree sort + seed T~0 = D^{-1/2} x
__global__ __launch_bounds__(1024) void k_prep(const float* __restrict__ x) {
    __shared__ int hist[64];
    __shared__ int base[64];
    int w0 = blockIdx.x * 1024;
    int tid = threadIdx.x;
    if (tid < 64) hist[tid] = 0;
    __syncthreads();
    int n = w0 + tid;
    int b = 63;
    if (n < NN) {
        int rp = g_rowptr[n] + g_boff[blockIdx.x];
        g_rowptr[n] = rp;
        g_cur[n] = rp;
        int d = g_deg[n];
        b = d < 63 ? d : 63;
        atomicAdd(&hist[b], 1);
        float dis = g_dis[n];
        const float4* xr = (const float4*)(x + (size_t)n * FIN);
        float4* tr = (float4*)(g_T[0] + (size_t)n * TSTR);
#pragma unroll
        for (int s = 0; s < 6; s++) {
            float4 v = __ldg(xr + s);
            tr[s] = make_float4(dis * v.x, dis * v.y, dis * v.z, dis * v.w);
        }
    }
    __syncthreads();
    if (tid == 0) {
        int acc = 0;
        for (int k = 0; k < 64; k++) { base[k] = acc; acc += hist[k]; }
    }
    __syncthreads();
    if (n < NN) {
        int pos = atomicAdd(&base[b], 1);
        g_ord[w0 + pos] = n;
    }
}

// scatter: CSR = src index only, 4 edges per thread
__global__ void k_scatter(const int4* __restrict__ row4, const int4* __restrict__ col4) {
    int i = blockIdx.x * blockDim.x + threadIdx.x;
    if (i >= EE / 4) return;
    int4 r = __ldg(row4 + i);
    int4 c = __ldg(col4 + i);
    g_csr[atomicAdd(&g_cur[c.x], 1)] = r.x;
    g_csr[atomicAdd(&g_cur[c.y], 1)] = r.y;
    g_csr[atomicAdd(&g_cur[c.z], 1)] = r.z;
    g_csr[atomicAdd(&g_cur[c.w], 1)] = r.w;
}

// ---------------- propagation: cooperative gather (frozen at round-11 form) ----
__global__ __launch_bounds__(256) void k_gather(int dsti, int prevI, int prev2I,
                                                float scl, int do_sub) {
    int t = blockIdx.x * blockDim.x + threadIdx.x;
    int grp = t / 6;
    if (grp >= NN) return;
    int sub = t - grp * 6;
    int node = __ldg(&g_ord[grp]);

    const float* src = g_T[prevI];

    int p  = __ldg(&g_rowptr[node]);
    int p1 = __ldg(&g_rowptr[node + 1]);

    float ax = 0.f, ay = 0.f, az = 0.f, aw = 0.f;   // chain A
    float bx = 0.f, by = 0.f, bz = 0.f, bw = 0.f;   // chain B

    for (; p + 3 < p1; p += 4) {
        int r0 = __ldg(&g_csr[p]);
        int r1 = __ldg(&g_csr[p + 1]);
        int r2 = __ldg(&g_csr[p + 2]);
        int r3 = __ldg(&g_csr[p + 3]);
        float4 v0 = __ldg((const float4*)(src + (size_t)r0 * TSTR) + sub);
        float4 v1 = __ldg((const float4*)(src + (size_t)r1 * TSTR) + sub);
        float4 v2 = __ldg((const float4*)(src + (size_t)r2 * TSTR) + sub);
        float4 v3 = __ldg((const float4*)(src + (size_t)r3 * TSTR) + sub);
        ax += v0.x + v2.x; ay += v0.y + v2.y; az += v0.z + v2.z; aw += v0.w + v2.w;
        bx += v1.x + v3.x; by += v1.y + v3.y; bz += v1.z + v3.z; bw += v1.w + v3.w;
    }
    for (; p < p1; p++) {
        int r0 = __ldg(&g_csr[p]);
        float4 v0 = __ldg((const float4*)(src + (size_t)r0 * TSTR) + sub);
        ax += v0.x; ay += v0.y; az += v0.z; aw += v0.w;
    }

    float coef = -scl * __ldg(&g_inv[node]);
    ax = coef * (ax + bx); ay = coef * (ay + by);
    az = coef * (az + bz); aw = coef * (aw + bw);
    if (do_sub) {
        float4 q = __ldg((const float4*)(g_T[prev2I] + (size_t)node * TSTR) + sub);
        ax -= q.x; ay -= q.y; az -= q.z; aw -= q.w;
    }
    ((float4*)(g_T[dsti] + (size_t)node * TSTR))[sub] = make_float4(ax, ay, az, aw);
}

// ---------------- h = [x | rs*T~1..rs*T~5] @ W[144,64] + b1 ; + BN stats ----------
// 4 nodes/thread x 16 cols/thread: each weight LDS.64 feeds 4 FFMA2 (LDS halved
// vs npt=2). tid&3 = col quarter, tid>>2 = node group. 128 nodes per block.
__global__ __launch_bounds__(128) void k_gemm(const float* __restrict__ x,
                                              const float* __restrict__ W1,
                                              const float* __restrict__ b1) {
    __shared__ float sW[KC * FIN * HH];   // 36 KB
    __shared__ float sRs[4][HH];
    __shared__ float sRq[4][HH];

    int tid = threadIdx.x;
    for (int i = tid; i < KC * FIN * HH; i += 128) sW[i] = W1[i];
    __syncthreads();

    int qc = tid & 3;                       // col quarter: cols [qc*16, qc*16+16)
    int nb = blockIdx.x * 128 + (tid >> 2) * 4;
    int nid[4];
    bool v[4], z[4];
    float rs[4];
#pragma unroll
    for (int m = 0; m < 4; m++) {
        nid[m] = nb + m;
        v[m] = (nid[m] < NN);
        rs[m] = v[m] ? __ldg(&g_rs[nid[m]]) : 0.f;
        z[m] = v[m] && (__ldg(&g_deg[nid[m]]) == 0);
    }

    unsigned long long acc[4][8];
#pragma unroll
    for (int m = 0; m < 4; m++)
#pragma unroll
        for (int j = 0; j < 8; j++) acc[m][j] = 0ull;

#pragma unroll
    for (int k = 0; k < KC; k++) {
        const float* base = (k == 0 ? x : g_T[k]);
        int str = (k == 0 ? FIN : TSTR);
#pragma unroll
        for (int i4 = 0; i4 < 6; i4++) {
            float4 av[4];
#pragma unroll
            for (int m = 0; m < 4; m++) {
                float4 a = v[m] ? __ldg((const float4*)(base + (size_t)nid[m] * str) + i4)
                                : make_float4(0.f, 0.f, 0.f, 0.f);
                float mm = (k == 0) ? 1.f : rs[m];
                av[m] = make_float4(mm * a.x, mm * a.y, mm * a.z, mm * a.w);
            }
#pragma unroll
            for (int t = 0; t < 4; t++) {
                int i = i4 * 4 + t;
                float sv[4] = { t == 0 ? av[0].x : t == 1 ? av[0].y : t == 2 ? av[0].z : av[0].w,
                                t == 0 ? av[1].x : t == 1 ? av[1].y : t == 2 ? av[1].z : av[1].w,
                                t == 0 ? av[2].x : t == 1 ? av[2].y : t == 2 ? av[2].z : av[2].w,
                                t == 0 ? av[3].x : t == 1 ? av[3].y : t == 2 ? av[3].z : av[3].w };
                unsigned long long p0 = pack2(sv[0], sv[0]);
                unsigned long long p1 = pack2(sv[1], sv[1]);
                unsigned long long p2 = pack2(sv[2], sv[2]);
                unsigned long long p3 = pack2(sv[3], sv[3]);
                const unsigned long long* wr =
                    (const unsigned long long*)&sW[(k * FIN + i) * HH + qc * 16];
#pragma unroll
                for (int j = 0; j < 8; j++) {
                    unsigned long long wj = wr[j];
                    ffma2(acc[0][j], p0, wj);
                    ffma2(acc[1][j], p1, wj);
                    ffma2(acc[2][j], p2, wj);
                    ffma2(acc[3][j], p3, wj);
                }
            }
        }
    }

    // rare deg==0 correction: scaled T~ are zero there, but true T2=-x, T4=+x
    if (z[0] | z[1] | z[2] | z[3]) {
        for (int i = 0; i < FIN; i++) {
            const float2* w2 = (const float2*)&sW[(2 * FIN + i) * HH + qc * 16];
            const float2* w4 = (const float2*)&sW[(4 * FIN + i) * HH + qc * 16];
            for (int j = 0; j < 8; j++) {
                float2 a2 = w2[j], a4 = w4[j];
                unsigned long long wd = pack2(a4.x - a2.x, a4.y - a2.y);
#pragma unroll
                for (int m = 0; m < 4; m++) {
                    if (z[m]) {
                        float xv = __ldg(&x[(size_t)nid[m] * FIN + i]);
                        ffma2(acc[m][j], pack2(xv, xv), wd);
                    }
                }
            }
        }
    }

    // bias, h store, local BN partials over this thread's 16 cols
    float s[16], qsum[16];
#pragma unroll
    for (int j = 0; j < 8; j++) {
        float b0 = __ldg(&b1[qc * 16 + 2 * j]);
        float b1v = __ldg(&b1[qc * 16 + 2 * j + 1]);
        float se = 0.f, so = 0.f, qe = 0.f, qo = 0.f;
#pragma unroll
        for (int m = 0; m < 4; m++) {
            float lo, hi;
            unpack2(acc[m][j], lo, hi);
            lo += b0; hi += b1v;
            if (v[m]) {
                se += lo; so += hi;
                qe += lo * lo; qo += hi * hi;
                ((float2*)(g_h + (size_t)nid[m] * HH + qc * 16))[j] = make_float2(lo, hi);
            }
        }
        s[2 * j] = se; s[2 * j + 1] = so;
        qsum[2 * j] = qe; qsum[2 * j + 1] = qo;
    }

    // reduce across lanes sharing the same col quarter (stride-4 classes)
    int lane = tid & 31, wid = tid >> 5;
#pragma unroll
    for (int j = 0; j < 16; j++) {
        float sv = s[j], qv = qsum[j];
#pragma unroll
        for (int off = 4; off < 32; off <<= 1) {
            sv += __shfl_xor_sync(0xffffffffu, sv, off);
            qv += __shfl_xor_sync(0xffffffffu, qv, off);
        }
        if (lane < 4) {
            sRs[wid][lane * 16 + j] = sv;
            sRq[wid][lane * 16 + j] = qv;
        }
    }
    __syncthreads();
    if (tid < HH) {
        float a = sRs[0][tid] + sRs[1][tid] + sRs[2][tid] + sRs[3][tid];
        float b = sRq[0][tid] + sRq[1][tid] + sRq[2][tid] + sRq[3][tid];
        atomicAdd(&g_sum[tid], a);
        atomicAdd(&g_sumsq[tid], b);
    }
}

__global__ void k_bnparam(const float* __restrict__ gamma, const float* __restrict__ beta) {
    int j = threadIdx.x;
    if (j < HH) {
        float inv_n = 1.f / (float)NN;
        float mean = g_sum[j] * inv_n;
        float var  = g_sumsq[j] * inv_n - mean * mean;
        float rstd = rsqrtf(var + EPSBN);
        float sc = gamma[j] * rstd;
        g_scale[j] = sc;
        g_shift[j] = beta[j] - mean * sc;
    }
}

__global__ __launch_bounds__(256) void k_final(const float* __restrict__ Wmix,
                                               const float* __restrict__ bmix,
                                               float* __restrict__ out) {
    __shared__ float sWm[HH * OD];
    __shared__ float sSc[HH], sSh[HH], sB[OD];
    int tid = threadIdx.x;
    for (int i = tid; i < HH * OD; i += 256) sWm[i] = Wmix[i];
    if (tid < HH) { sSc[tid] = g_scale[tid]; sSh[tid] = g_shift[tid]; }
    if (tid < OD) sB[tid] = bmix[tid];
    __syncthreads();

    int n = blockIdx.x * 256 + tid;
    if (n >= NN) return;

    float o0 = sB[0], o1 = sB[1], o2 = sB[2], o3 = sB[3], o4 = sB[4], o5 = sB[5];
    const float4* hp = (const float4*)(g_h + (size_t)n * HH);
#pragma unroll
    for (int j4 = 0; j4 < 16; j4++) {
        float4 hv = hp[j4];
        float hv4[4] = {hv.x, hv.y, hv.z, hv.w};
#pragma unroll
        for (int t = 0; t < 4; t++) {
            int j = 4 * j4 + t;
            float val = fmaxf(hv4[t] * sSc[j] + sSh[j], 0.f);
            const float* wm = &sWm[j * OD];
            o0 += val * wm[0]; o1 += val * wm[1]; o2 += val * wm[2];
            o3 += val * wm[3]; o4 += val * wm[4]; o5 += val * wm[5];
        }
    }
    float* op = out + (size_t)n * OD;
    op[0] = o0; op[1] = o1; op[2] = o2; op[3] = o3; op[4] = o4; op[5] = o5;
}

// ---------------- launch ----------------
extern "C" void kernel_launch(void* const* d_in, const int* in_sizes, int n_in,
                              void* d_out, int out_size) {
    const float* x     = (const float*)d_in[0];
    const int*   ei    = (const int*)  d_in[1];
    const float* W1    = (const float*)d_in[2];
    const float* b1    = (const float*)d_in[3];
    const float* gamma = (const float*)d_in[4];
    const float* beta  = (const float*)d_in[5];
    const float* Wmix  = (const float*)d_in[6];
    const float* bmix  = (const float*)d_in[7];
    float* out = (float*)d_out;

    const int* row = ei;
    const int* col = ei + EE;

    const int TB = 256;
    int gN  = (NN + TB - 1) / TB;
    int gE4 = (EE / 4 + TB - 1) / TB;
    int gG  = (6 * NN + TB - 1) / TB;

    k_zero<<<gN, TB>>>();
    k_deg<<<gE4, TB>>>((const int4*)col);
    k_scan1<<<NB, 1024>>>();
    k_scan2<<<1, 512>>>();
    k_prep<<<NB, 1024>>>(x);
    k_scatter<<<gE4, TB>>>((const int4*)row, (const int4*)col);

    // scaled-space Chebyshev recurrence
    k_gather<<<gG, TB>>>(1, 0, 0, 1.f, 0);   // T~1 = -(1/deg) sum T~0
    k_gather<<<gG, TB>>>(2, 1, 0, 2.f, 1);   // T~2 = -(2/deg) sum T~1 - T~0
    k_gather<<<gG, TB>>>(3, 2, 1, 2.f, 1);
    k_gather<<<gG, TB>>>(4, 3, 2, 2.f, 1);
    k_gather<<<gG, TB>>>(5, 4, 3, 2.f, 1);

    k_gemm<<<(NN + 127) / 128, 128>>>(x, W1, b1);
    k_bnparam<<<1, HH>>>(gamma, beta);
    k_final<<<gN, TB>>>(Wmix, bmix, out);
}